// round 16
// baseline (speedup 1.0000x reference)
#include <cuda_runtime.h>
#include <cuda_bf16.h>
#include <math.h>
#include <stdint.h>

#define Bn 8
#define Ln 64
#define Dn 256
#define Kn 32

// Scratch (device globals -- allocation is forbidden)
__device__ float g_S[Bn*Kn*Ln*Ln];             // 4 MB per-k scaled contributions

// ---- mma.sync / ldmatrix (family-safe) ----
__device__ __forceinline__ void ldsm_x4(uint32_t* r, uint32_t addr){
    asm volatile("ldmatrix.sync.aligned.m8n8.x4.shared.b16 {%0,%1,%2,%3}, [%4];"
        : "=r"(r[0]),"=r"(r[1]),"=r"(r[2]),"=r"(r[3]) : "r"(addr));
}
__device__ __forceinline__ void ldsm_x4t(uint32_t* r, uint32_t addr){
    asm volatile("ldmatrix.sync.aligned.m8n8.x4.trans.shared.b16 {%0,%1,%2,%3}, [%4];"
        : "=r"(r[0]),"=r"(r[1]),"=r"(r[2]),"=r"(r[3]) : "r"(addr));
}
__device__ __forceinline__ void mma_bf16(float* c, const uint32_t* a, uint32_t b0, uint32_t b1){
    asm volatile("mma.sync.aligned.m16n8k16.row.col.f32.bf16.bf16.f32 "
        "{%0,%1,%2,%3}, {%4,%5,%6,%7}, {%8,%9}, {%0,%1,%2,%3};"
        : "+f"(c[0]), "+f"(c[1]), "+f"(c[2]), "+f"(c[3])
        : "r"(a[0]), "r"(a[1]), "r"(a[2]), "r"(a[3]), "r"(b0), "r"(b1));
}
__device__ __forceinline__ uint32_t smem_u32_of(const void* p){
    uint32_t a;
    asm("{ .reg .u64 t; cvta.to.shared.u64 t, %1; cvt.u32.u64 %0, t; }" : "=r"(a) : "l"(p));
    return a;
}
__device__ __forceinline__ void bf16split4(float4 v, uint2& hv, uint2& lv){
    __nv_bfloat16 h0=__float2bfloat16(v.x), h1=__float2bfloat16(v.y);
    __nv_bfloat16 h2=__float2bfloat16(v.z), h3=__float2bfloat16(v.w);
    __nv_bfloat16 l0=__float2bfloat16(v.x-__bfloat162float(h0));
    __nv_bfloat16 l1=__float2bfloat16(v.y-__bfloat162float(h1));
    __nv_bfloat16 l2=__float2bfloat16(v.z-__bfloat162float(h2));
    __nv_bfloat16 l3=__float2bfloat16(v.w-__bfloat162float(h3));
    hv.x = (uint32_t)__bfloat16_as_ushort(h0) | ((uint32_t)__bfloat16_as_ushort(h1)<<16);
    hv.y = (uint32_t)__bfloat16_as_ushort(h2) | ((uint32_t)__bfloat16_as_ushort(h3)<<16);
    lv.x = (uint32_t)__bfloat16_as_ushort(l0) | ((uint32_t)__bfloat16_as_ushort(l1)<<16);
    lv.y = (uint32_t)__bfloat16_as_ushort(l2) | ((uint32_t)__bfloat16_as_ushort(l3)<<16);
}
__device__ __forceinline__ void split_pair(float x, float y, uint32_t& h, uint32_t& l){
    __nv_bfloat16 hx=__float2bfloat16(x), hy=__float2bfloat16(y);
    __nv_bfloat16 lx=__float2bfloat16(x-__bfloat162float(hx));
    __nv_bfloat16 ly=__float2bfloat16(y-__bfloat162float(hy));
    h = (uint32_t)__bfloat16_as_ushort(hx) | ((uint32_t)__bfloat16_as_ushort(hy)<<16);
    l = (uint32_t)__bfloat16_as_ushort(lx) | ((uint32_t)__bfloat16_as_ushort(ly)<<16);
}

// ===================== fused kernel ==========================================
// block = (b,k).  All bf16 splitting happens IN-KERNEL (no prep kernel):
//   - arg1/arg2: fp32 LDG -> split -> smem  (4096 float4s = 16/thread!)
//   - Wb: per-chunk fp32 LDG -> regs (latency hidden under MMA) -> split -> smem
// Phase 1 (verified): T = arg1[b]@Wb[k] bf16 mma 3-pass, frags (x4.trans B).
// Phase 2 (verified): btp = T@arg2^T via mma; A-frags from phase-1 C-frags.
#define AH_B 0
#define AL_B 33792
#define WH_B 67584
#define WL_B 84480
#define A2H_B 0
#define A2L_B 33792
#define PC_F 16896
#define PCS 72
#define P2_F 25344
#define WCOL_F 25600
#define SMEM_BYTES 106496
__global__ void __launch_bounds__(256,2) fused_kernel(
        const float* __restrict__ arg1, const float* __restrict__ arg2,
        const float* __restrict__ Wb,
        const float* __restrict__ Wd, const float* __restrict__ Wg,
        const float* __restrict__ bgp, const float* __restrict__ bp,
        const float* __restrict__ up){
    extern __shared__ float sh[];
    char*  smc  = (char*)sh;
    float* PC   = sh + PC_F;                // [64][72] cross-warp C partials
    float* P2   = sh + P2_F;                // a1d[64] a1g[64] a2d[64] a2g[64]
    float* Wcol = sh + WCOL_F;              // [4][256]

    int b = blockIdx.x >> 5, k = blockIdx.x & 31;
    int tid = threadIdx.x;
    int wid = tid >> 5, lane = tid & 31;
    int wm = wid & 3, wf = wid >> 2;        // warp tile: m0 = 16*wm, f-half wf
    int m0 = 16*wm;
    int g = lane >> 2, tg = lane & 3;
    uint32_t smem0 = smem_u32_of(sh);

    // ---- Wcol (Wd/Wg columns for this k) ----
    for(int i = tid; i < 4*Dn; i += 256){
        int arr = i >> 8, e = i & 255;
        float v;
        if(arr==0)      v = Wd[e*Kn + k];
        else if(arr==1) v = Wg[e*Kn + k];
        else if(arr==2) v = Wd[(Dn+e)*Kn + k];
        else            v = Wg[(Dn+e)*Kn + k];
        Wcol[i] = v;
    }

    const float* WkF = Wb + (size_t)k*Dn*Dn;
    const float* A1f = arg1 + b*Ln*Dn;

    // ---- convert arg1 fp32 -> AH/AL bf16 smem (ALL 4096 float4s) ----
    #pragma unroll
    for(int r = 0; r < 16; r++){
        int idx = tid + 256*r;              // 0..4095 float4s over 64x256
        int m = idx >> 6, c4 = idx & 63;
        float4 v = *(const float4*)(A1f + m*Dn + 4*c4);
        uint2 hv, lv;
        bf16split4(v, hv, lv);
        *(uint2*)(smc + AH_B + m*528 + c4*8) = hv;
        *(uint2*)(smc + AL_B + m*528 + c4*8) = lv;
    }

    // ---- convert W chunk 0 -> WH/WL buffer 0 (16x256 = 1024 float4s) ----
    {
        #pragma unroll
        for(int r = 0; r < 4; r++){
            int idx = tid + 256*r;
            int row = idx >> 6, f4 = idx & 63;
            float4 v = *(const float4*)(WkF + row*Dn + 4*f4);
            uint2 hv, lv;
            bf16split4(v, hv, lv);
            *(uint2*)(smc + WH_B + row*528 + f4*8) = hv;
            *(uint2*)(smc + WL_B + row*528 + f4*8) = lv;
        }
    }
    __syncthreads();                        // AH/AL + W chunk 0 visible

    // ---------- phase 1: 16 ksteps of 16e, double-buffered W ----------
    float acc[16][4];
    #pragma unroll
    for(int nt = 0; nt < 16; nt++)
        #pragma unroll
        for(int q = 0; q < 4; q++) acc[nt][q] = 0.f;

    uint32_t aBaseH = smem0 + AH_B + (m0 + (lane & 15))*528;
    uint32_t aBaseL = smem0 + AL_B + (m0 + (lane & 15))*528;
    uint32_t wRow4  = (lane & 15)*528 + wf*256 + ((lane >> 4) & 1)*16;

    for(int c = 0; c < 16; c++){
        int bi = c & 1;
        // issue fp32 loads for chunk c+1 early (latency hidden under MMA)
        float4 wv[4];
        if(c < 15){
            const float* src = WkF + (c+1)*16*Dn;
            #pragma unroll
            for(int r = 0; r < 4; r++){
                int idx = tid + 256*r;
                int row = idx >> 6, f4 = idx & 63;
                wv[r] = *(const float4*)(src + row*Dn + 4*f4);
            }
        }

        uint32_t cofs = (uint32_t)(c*32 + ((lane >> 4)*16));
        uint32_t ah[4], al[4];
        ldsm_x4(ah, aBaseH + cofs);
        ldsm_x4(al, aBaseL + cofs);
        uint32_t wH = smem0 + WH_B + bi*8448 + wRow4;
        uint32_t wL = smem0 + WL_B + bi*8448 + wRow4;
        #pragma unroll
        for(int nt2 = 0; nt2 < 8; nt2++){
            uint32_t bh[4], bl[4];
            ldsm_x4t(bh, wH + nt2*32);
            ldsm_x4t(bl, wL + nt2*32);
            mma_bf16(acc[2*nt2],   ah, bh[0], bh[1]);
            mma_bf16(acc[2*nt2],   al, bh[0], bh[1]);
            mma_bf16(acc[2*nt2],   ah, bl[0], bl[1]);
            mma_bf16(acc[2*nt2+1], ah, bh[2], bh[3]);
            mma_bf16(acc[2*nt2+1], al, bh[2], bh[3]);
            mma_bf16(acc[2*nt2+1], ah, bl[2], bl[3]);
        }

        if(c < 15){
            int bj = (c+1) & 1;
            #pragma unroll
            for(int r = 0; r < 4; r++){
                int idx = tid + 256*r;
                int row = idx >> 6, f4 = idx & 63;
                uint2 hv, lv;
                bf16split4(wv[r], hv, lv);
                *(uint2*)(smc + WH_B + bj*8448 + row*528 + f4*8) = hv;
                *(uint2*)(smc + WL_B + bj*8448 + row*528 + f4*8) = lv;
            }
        }
        __syncthreads();                    // chunk c+1 visible; buffer bi reusable
    }

    // ---- convert arg2 fp32 -> A2H/A2L (ALL 4096 float4s; overlays A1) ----
    const float* A2f = arg2 + b*Ln*Dn;
    #pragma unroll
    for(int r = 0; r < 16; r++){
        int idx = tid + 256*r;
        int n = idx >> 6, c4 = idx & 63;
        float4 v = *(const float4*)(A2f + n*Dn + 4*c4);
        uint2 hv, lv;
        bf16split4(v, hv, lv);
        *(uint2*)(smc + A2H_B + n*528 + c4*8) = hv;
        *(uint2*)(smc + A2L_B + n*528 + c4*8) = lv;
    }

    // ---- projections: 256 warp-dots (fp32, gmem rows are L2-hot) ----
    {
        #pragma unroll 1
        for(int j = 0; j < 32; j++){
            int dd = wid*32 + j;            // 0..255
            int arr = dd >> 6, m = dd & 63; // 0:a1d 1:a1g 2:a2d 3:a2g
            const float* row = ((arr < 2) ? arg1 : arg2) + (b*Ln + m)*Dn;
            float s = 0.f;
            #pragma unroll
            for(int t = 0; t < 8; t++){
                int e = lane + 32*t;
                s = fmaf(row[e], Wcol[arr*Dn + e], s);
            }
            #pragma unroll
            for(int off = 16; off; off >>= 1) s += __shfl_xor_sync(0xFFFFFFFFu, s, off);
            if(lane == 0) P2[dd] = s;
        }
    }
    __syncthreads();                        // A2 tiles + P2 visible

    // ---------- phase 2: btp = T @ arg2^T via mma (verified) ----------
    float C[8][4];
    #pragma unroll
    for(int nt = 0; nt < 8; nt++)
        #pragma unroll
        for(int q = 0; q < 4; q++) C[nt][q] = 0.f;

    #pragma unroll
    for(int kc = 0; kc < 8; kc++){
        uint32_t ah[4], al[4];
        split_pair(acc[2*kc][0],   acc[2*kc][1],   ah[0], al[0]);
        split_pair(acc[2*kc][2],   acc[2*kc][3],   ah[1], al[1]);
        split_pair(acc[2*kc+1][0], acc[2*kc+1][1], ah[2], al[2]);
        split_pair(acc[2*kc+1][2], acc[2*kc+1][3], ah[3], al[3]);
        int fbyte = wf*256 + kc*32 + tg*4;
        #pragma unroll
        for(int nt = 0; nt < 8; nt++){
            int rowb = (8*nt + g)*528 + fbyte;
            uint32_t bh0 = *(const uint32_t*)(smc + A2H_B + rowb);
            uint32_t bh1 = *(const uint32_t*)(smc + A2H_B + rowb + 16);
            uint32_t bl0 = *(const uint32_t*)(smc + A2L_B + rowb);
            uint32_t bl1 = *(const uint32_t*)(smc + A2L_B + rowb + 16);
            mma_bf16(C[nt], ah, bh0, bh1);
            mma_bf16(C[nt], al, bh0, bh1);
            mma_bf16(C[nt], ah, bl0, bl1);
        }
    }

    // ---- cross-warp combine (wf=0 writes, wf=1 adds + epilogue) ----
    if(wf == 0){
        #pragma unroll
        for(int nt = 0; nt < 8; nt++){
            int col = 8*nt + 2*tg;
            *(float2*)&PC[(m0+g)*PCS + col]   = make_float2(C[nt][0], C[nt][1]);
            *(float2*)&PC[(m0+g+8)*PCS + col] = make_float2(C[nt][2], C[nt][3]);
        }
    }
    __syncthreads();

    if(wf == 1){
        float bgk = bgp[k], bk = bp[k], uk = up[k];
        float* Sb = g_S + (size_t)(b*Kn + k)*Ln*Ln;
        float a1d0 = P2[m0+g],      a1g0 = P2[64+m0+g];
        float a1d1 = P2[m0+g+8],    a1g1 = P2[64+m0+g+8];
        #pragma unroll
        for(int nt = 0; nt < 8; nt++){
            int col = 8*nt + 2*tg;
            float2 p0 = *(float2*)&PC[(m0+g)*PCS + col];
            float2 p1 = *(float2*)&PC[(m0+g+8)*PCS + col];
            float v00 = C[nt][0] + p0.x, v01 = C[nt][1] + p0.y;
            float v10 = C[nt][2] + p1.x, v11 = C[nt][3] + p1.y;
            float a2d0 = P2[128+col], a2d1 = P2[128+col+1];
            float a2g0 = P2[192+col], a2g1 = P2[192+col+1];
            float r00, r01, r10, r11;
            {
                float sln = tanhf(a1d0 + a2d0);
                float gt  = 1.0f/(1.0f + expf(-(a1g0 + a2g0 + bgk)));
                r00 = uk*(gt*v00 + (1.0f-gt)*sln + bk);
                sln = tanhf(a1d0 + a2d1);
                gt  = 1.0f/(1.0f + expf(-(a1g0 + a2g1 + bgk)));
                r01 = uk*(gt*v01 + (1.0f-gt)*sln + bk);
                sln = tanhf(a1d1 + a2d0);
                gt  = 1.0f/(1.0f + expf(-(a1g1 + a2g0 + bgk)));
                r10 = uk*(gt*v10 + (1.0f-gt)*sln + bk);
                sln = tanhf(a1d1 + a2d1);
                gt  = 1.0f/(1.0f + expf(-(a1g1 + a2g1 + bgk)));
                r11 = uk*(gt*v11 + (1.0f-gt)*sln + bk);
            }
            *(float2*)&Sb[(m0+g)*Ln + col]   = make_float2(r00, r01);
            *(float2*)&Sb[(m0+g+8)*Ln + col] = make_float2(r10, r11);
        }
    }
}

// ---- deterministic split-k reduction: 2 threads per output ----
__global__ void reduce_kernel(float* __restrict__ out){
    __shared__ float red[128];
    int tid = threadIdx.x;
    int s = tid >> 1, h = tid & 1;
    int gmn = blockIdx.x*128 + s;           // 0..32767
    int b = gmn >> 12, mn = gmn & 4095;
    const float* p = g_S + (size_t)b*Kn*4096 + mn + h*16*4096;
    float acc = 0.f;
    #pragma unroll
    for(int kk = 0; kk < 16; kk++) acc += p[kk*4096];
    if(h) red[s] = acc;
    __syncthreads();
    if(!h) out[gmn] = acc + red[s];
}

extern "C" void kernel_launch(void* const* d_in, const int* in_sizes, int n_in,
                              void* d_out, int out_size){
    const float *arg1=0,*arg2=0,*Wb=0,*Wd=0,*Wg=0,*bg=0,*bb=0,*u=0;
    int nBig=0, nMed=0, nSmall=0;
    for(int i=0;i<n_in;i++){
        int sz = in_sizes[i];
        const float* pp = (const float*)d_in[i];
        if(sz == Kn*Dn*Dn)          Wb = pp;
        else if(sz == Bn*Ln*Dn)     { if(nBig++==0) arg1=pp; else arg2=pp; }
        else if(sz == 2*Dn*Kn)      { if(nMed++==0) Wd=pp;   else Wg=pp; }
        else if(sz == Kn)           { if(nSmall==0) bg=pp; else if(nSmall==1) bb=pp; else u=pp; nSmall++; }
    }
    float* out = (float*)d_out;

    static int attr_done = 0;
    if(!attr_done){
        cudaFuncSetAttribute(fused_kernel, cudaFuncAttributeMaxDynamicSharedMemorySize, SMEM_BYTES);
        attr_done = 1;
    }

    fused_kernel<<<Bn*Kn, 256, SMEM_BYTES>>>(arg1, arg2, Wb, Wd, Wg, bg, bb, u);
    reduce_kernel<<<256, 256>>>(out);
}

// round 17
// speedup vs baseline: 1.2017x; 1.2017x over previous
#include <cuda_runtime.h>
#include <cuda_fp16.h>
#include <math.h>
#include <stdint.h>

#define Bn 8
#define Ln 64
#define Dn 256
#define Kn 32

// Scratch (device globals -- allocation is forbidden)
__device__ float g_S[Bn*Kn*Ln*Ln];             // 4 MB per-k scaled contributions
__device__ unsigned short g_Wh [Kn*Dn*Dn];     // fp16 hi of Wb [k][e][f]  (lo not needed)
__device__ unsigned short g_A1h[Bn*Ln*Dn];     // fp16 hi of arg1 [b][m][e]
__device__ unsigned short g_A1l[Bn*Ln*Dn];     // fp16 lo of arg1
__device__ unsigned short g_A2h[Bn*Ln*Dn];     // fp16 hi of arg2 [b][n][f] (lo not needed)

// ---- cp.async ----
__device__ __forceinline__ void cp16(uint32_t dst, const void* src){
    asm volatile("cp.async.cg.shared.global [%0], [%1], 16;" :: "r"(dst), "l"(src));
}
#define CP_COMMIT() asm volatile("cp.async.commit_group;")
#define CP_WAIT0()  asm volatile("cp.async.wait_group 0;")
#define CP_WAIT1()  asm volatile("cp.async.wait_group 1;")
// ---- mma.sync / ldmatrix (family-safe) ----
__device__ __forceinline__ void ldsm_x4(uint32_t* r, uint32_t addr){
    asm volatile("ldmatrix.sync.aligned.m8n8.x4.shared.b16 {%0,%1,%2,%3}, [%4];"
        : "=r"(r[0]),"=r"(r[1]),"=r"(r[2]),"=r"(r[3]) : "r"(addr));
}
__device__ __forceinline__ void ldsm_x4t(uint32_t* r, uint32_t addr){
    asm volatile("ldmatrix.sync.aligned.m8n8.x4.trans.shared.b16 {%0,%1,%2,%3}, [%4];"
        : "=r"(r[0]),"=r"(r[1]),"=r"(r[2]),"=r"(r[3]) : "r"(addr));
}
__device__ __forceinline__ void mma_f16(float* c, const uint32_t* a, uint32_t b0, uint32_t b1){
    asm volatile("mma.sync.aligned.m16n8k16.row.col.f32.f16.f16.f32 "
        "{%0,%1,%2,%3}, {%4,%5,%6,%7}, {%8,%9}, {%0,%1,%2,%3};"
        : "+f"(c[0]), "+f"(c[1]), "+f"(c[2]), "+f"(c[3])
        : "r"(a[0]), "r"(a[1]), "r"(a[2]), "r"(a[3]), "r"(b0), "r"(b1));
}
__device__ __forceinline__ uint32_t smem_u32_of(const void* p){
    uint32_t a;
    asm("{ .reg .u64 t; cvta.to.shared.u64 t, %1; cvt.u32.u64 %0, t; }" : "=r"(a) : "l"(p));
    return a;
}
__device__ __forceinline__ void f16split4(float4 v, uint2& hv, uint2& lv){
    __half h0=__float2half_rn(v.x), h1=__float2half_rn(v.y);
    __half h2=__float2half_rn(v.z), h3=__float2half_rn(v.w);
    __half l0=__float2half_rn(v.x-__half2float(h0));
    __half l1=__float2half_rn(v.y-__half2float(h1));
    __half l2=__float2half_rn(v.z-__half2float(h2));
    __half l3=__float2half_rn(v.w-__half2float(h3));
    hv.x = (uint32_t)__half_as_ushort(h0) | ((uint32_t)__half_as_ushort(h1)<<16);
    hv.y = (uint32_t)__half_as_ushort(h2) | ((uint32_t)__half_as_ushort(h3)<<16);
    lv.x = (uint32_t)__half_as_ushort(l0) | ((uint32_t)__half_as_ushort(l1)<<16);
    lv.y = (uint32_t)__half_as_ushort(l2) | ((uint32_t)__half_as_ushort(l3)<<16);
}
__device__ __forceinline__ void f16hi4(float4 v, uint2& hv){
    __half h0=__float2half_rn(v.x), h1=__float2half_rn(v.y);
    __half h2=__float2half_rn(v.z), h3=__float2half_rn(v.w);
    hv.x = (uint32_t)__half_as_ushort(h0) | ((uint32_t)__half_as_ushort(h1)<<16);
    hv.y = (uint32_t)__half_as_ushort(h2) | ((uint32_t)__half_as_ushort(h3)<<16);
}
__device__ __forceinline__ void split_pair_f16(float x, float y, uint32_t& h, uint32_t& l){
    __half hx=__float2half_rn(x), hy=__float2half_rn(y);
    __half lx=__float2half_rn(x-__half2float(hx));
    __half ly=__float2half_rn(y-__half2float(hy));
    h = (uint32_t)__half_as_ushort(hx) | ((uint32_t)__half_as_ushort(hy)<<16);
    l = (uint32_t)__half_as_ushort(lx) | ((uint32_t)__half_as_ushort(ly)<<16);
}

// ---- K0: fp16 splits (W: hi only; arg1: hi+lo; arg2: hi only) ----
__device__ __forceinline__ void prep_one(int idx, const float* Wb, const float* arg1,
                                         const float* arg2){
    const int nW = Kn*Dn*Dn/4;                       // 524288
    const int nA = Bn*Ln*Dn/4;                       // 32768
    if(idx < nW){
        uint2 hv;
        f16hi4(((const float4*)Wb)[idx], hv);
        ((uint2*)g_Wh)[idx] = hv;
    } else if(idx < nW + nA){
        int j = idx - nW;
        uint2 hv, lv;
        f16split4(((const float4*)arg1)[j], hv, lv);
        ((uint2*)g_A1h)[j] = hv;  ((uint2*)g_A1l)[j] = lv;
    } else if(idx < nW + 2*nA){
        int j = idx - nW - nA;
        uint2 hv;
        f16hi4(((const float4*)arg2)[j], hv);
        ((uint2*)g_A2h)[j] = hv;
    }
}
__global__ void prep_kernel(const float* __restrict__ Wb, const float* __restrict__ arg1,
                            const float* __restrict__ arg2){
    int i0 = blockIdx.x*blockDim.x + threadIdx.x;    // 0..294911
    prep_one(i0, Wb, arg1, arg2);
    prep_one(i0 + 294912, Wb, arg1, arg2);
}

// ===================== fused kernel ==========================================
// block = (b,k). Phase 1: T = arg1[b]@Wb[k], fp16 2-pass (Ah+Al)@Wh, fp32 acc.
// Phase 2: btp = T@arg2^T, fp16 2-pass (Th+Tl)@A2h; A-frags from phase-1 C-frags.
// smem (bytes):
//   phase-1: AH @0 (64x528=33792); AL @33792; WH 2x8448 @67584 -> end 84480
//   phase-2 overlay: A2H @0 (33792); PC f32 [64][72] @67584 (18432)
//   tails:   P2 (256 f32) @101376... kept at same offsets as verified layout
#define AH_B 0
#define AL_B 33792
#define WH_B 67584
#define A2H_B 0
#define PC_F 16896
#define PCS 72
#define P2_F 25344
#define WCOL_F 25600
#define SMEM_BYTES 106496
__global__ void __launch_bounds__(256,2) fused_kernel(
        const float* __restrict__ arg1, const float* __restrict__ arg2,
        const float* __restrict__ Wd, const float* __restrict__ Wg,
        const float* __restrict__ bgp, const float* __restrict__ bp,
        const float* __restrict__ up){
    extern __shared__ float sh[];
    char*  smc  = (char*)sh;
    float* PC   = sh + PC_F;                // [64][72] cross-warp C partials
    float* P2   = sh + P2_F;                // a1d[64] a1g[64] a2d[64] a2g[64]
    float* Wcol = sh + WCOL_F;              // [4][256]

    int b = blockIdx.x >> 5, k = blockIdx.x & 31;
    int tid = threadIdx.x;
    int wid = tid >> 5, lane = tid & 31;
    int wm = wid & 3, wf = wid >> 2;        // warp tile: m0 = 16*wm, f-half wf
    int m0 = 16*wm;
    int g = lane >> 2, tg = lane & 3;
    uint32_t smem0 = smem_u32_of(sh);

    // ---- Wcol (Wd/Wg columns for this k) ----
    for(int i = tid; i < 4*Dn; i += 256){
        int arr = i >> 8, e = i & 255;
        float v;
        if(arr==0)      v = Wd[e*Kn + k];
        else if(arr==1) v = Wg[e*Kn + k];
        else if(arr==2) v = Wd[(Dn+e)*Kn + k];
        else            v = Wg[(Dn+e)*Kn + k];
        Wcol[i] = v;
    }

    // ---- cp.async: A1 (hi/lo) + W chunk 0 (hi only) ----
    const char* a1hB = (const char*)g_A1h + (size_t)(b*Ln)*Dn*2;
    const char* a1lB = (const char*)g_A1l + (size_t)(b*Ln)*Dn*2;
    #pragma unroll
    for(int r = 0; r < 8; r++){
        int idx = tid + 256*r;              // 0..2047
        int m = idx >> 5, ch = idx & 31;
        cp16(smem0 + AH_B + m*528 + ch*16, a1hB + m*512 + ch*16);
        cp16(smem0 + AL_B + m*528 + ch*16, a1lB + m*512 + ch*16);
    }
    const char* whB = (const char*)g_Wh + (size_t)k*Dn*Dn*2;
    #pragma unroll
    for(int r = 0; r < 2; r++){
        int idx = tid + 256*r;              // 0..511
        int row = idx >> 5, ch = idx & 31;
        cp16(smem0 + WH_B + row*528 + ch*16, whB + row*512 + ch*16);
    }
    CP_COMMIT();

    // ---------- phase 1: 16 ksteps of 16e, double-buffered W ----------
    float acc[16][4];
    #pragma unroll
    for(int nt = 0; nt < 16; nt++)
        #pragma unroll
        for(int q = 0; q < 4; q++) acc[nt][q] = 0.f;

    uint32_t aBaseH = smem0 + AH_B + (m0 + (lane & 15))*528;
    uint32_t aBaseL = smem0 + AL_B + (m0 + (lane & 15))*528;
    uint32_t wRow4  = (lane & 15)*528 + wf*256 + ((lane >> 4) & 1)*16;

    for(int c = 0; c < 16; c++){
        int bi = c & 1;
        if(c < 15){
            int bj = (c+1) & 1, e16 = (c+1)*16;
            #pragma unroll
            for(int r = 0; r < 2; r++){
                int idx = tid + 256*r;
                int row = idx >> 5, ch = idx & 31;
                cp16(smem0 + WH_B + bj*8448 + row*528 + ch*16, whB + (e16+row)*512 + ch*16);
            }
            CP_COMMIT();
            CP_WAIT1();
        } else {
            CP_WAIT0();
        }
        __syncthreads();

        uint32_t cofs = (uint32_t)(c*32 + ((lane >> 4)*16));
        uint32_t ah[4], al[4];
        ldsm_x4(ah, aBaseH + cofs);
        ldsm_x4(al, aBaseL + cofs);
        uint32_t wH = smem0 + WH_B + bi*8448 + wRow4;
        #pragma unroll
        for(int nt2 = 0; nt2 < 8; nt2++){
            uint32_t bh[4];
            ldsm_x4t(bh, wH + nt2*32);      // covers nt=2*nt2 (r0,r1) and 2*nt2+1 (r2,r3)
            mma_f16(acc[2*nt2],   ah, bh[0], bh[1]);
            mma_f16(acc[2*nt2],   al, bh[0], bh[1]);
            mma_f16(acc[2*nt2+1], ah, bh[2], bh[3]);
            mma_f16(acc[2*nt2+1], al, bh[2], bh[3]);
        }
        __syncthreads();
    }

    // ---- cp.async: arg2 fp16 hi into freed A region ----
    const char* a2hB = (const char*)g_A2h + (size_t)(b*Ln)*Dn*2;
    #pragma unroll
    for(int r = 0; r < 8; r++){
        int idx = tid + 256*r;
        int n = idx >> 5, ch = idx & 31;
        cp16(smem0 + A2H_B + n*528 + ch*16, a2hB + n*512 + ch*16);
    }
    CP_COMMIT();

    // ---- projections: 256 warp-dots (fp32, gmem rows are L2-hot) ----
    {
        #pragma unroll 1
        for(int j = 0; j < 32; j++){
            int dd = wid*32 + j;            // 0..255
            int arr = dd >> 6, m = dd & 63; // 0:a1d 1:a1g 2:a2d 3:a2g
            const float* row = ((arr < 2) ? arg1 : arg2) + (b*Ln + m)*Dn;
            float s = 0.f;
            #pragma unroll
            for(int t = 0; t < 8; t++){
                int e = lane + 32*t;
                s = fmaf(row[e], Wcol[arr*Dn + e], s);
            }
            #pragma unroll
            for(int off = 16; off; off >>= 1) s += __shfl_xor_sync(0xFFFFFFFFu, s, off);
            if(lane == 0) P2[dd] = s;
        }
    }
    CP_WAIT0();
    __syncthreads();                        // A2 tile + P2 visible

    // ---------- phase 2: btp = T @ arg2^T via fp16 mma 2-pass ----------
    float C[8][4];
    #pragma unroll
    for(int nt = 0; nt < 8; nt++)
        #pragma unroll
        for(int q = 0; q < 4; q++) C[nt][q] = 0.f;

    #pragma unroll
    for(int kc = 0; kc < 8; kc++){
        uint32_t th[4], tl[4];
        split_pair_f16(acc[2*kc][0],   acc[2*kc][1],   th[0], tl[0]);
        split_pair_f16(acc[2*kc][2],   acc[2*kc][3],   th[1], tl[1]);
        split_pair_f16(acc[2*kc+1][0], acc[2*kc+1][1], th[2], tl[2]);
        split_pair_f16(acc[2*kc+1][2], acc[2*kc+1][3], th[3], tl[3]);
        int fbyte = wf*256 + kc*32 + tg*4;
        #pragma unroll
        for(int nt = 0; nt < 8; nt++){
            int rowb = (8*nt + g)*528 + fbyte;
            uint32_t bh0 = *(const uint32_t*)(smc + A2H_B + rowb);
            uint32_t bh1 = *(const uint32_t*)(smc + A2H_B + rowb + 16);
            mma_f16(C[nt], th, bh0, bh1);
            mma_f16(C[nt], tl, bh0, bh1);
        }
    }

    // ---- cross-warp combine (wf=0 writes, wf=1 adds + epilogue) ----
    if(wf == 0){
        #pragma unroll
        for(int nt = 0; nt < 8; nt++){
            int col = 8*nt + 2*tg;
            *(float2*)&PC[(m0+g)*PCS + col]   = make_float2(C[nt][0], C[nt][1]);
            *(float2*)&PC[(m0+g+8)*PCS + col] = make_float2(C[nt][2], C[nt][3]);
        }
    }
    __syncthreads();

    if(wf == 1){
        float bgk = bgp[k], bk = bp[k], uk = up[k];
        float* Sb = g_S + (size_t)(b*Kn + k)*Ln*Ln;
        float a1d0 = P2[m0+g],      a1g0 = P2[64+m0+g];
        float a1d1 = P2[m0+g+8],    a1g1 = P2[64+m0+g+8];
        #pragma unroll
        for(int nt = 0; nt < 8; nt++){
            int col = 8*nt + 2*tg;
            float2 p0 = *(float2*)&PC[(m0+g)*PCS + col];
            float2 p1 = *(float2*)&PC[(m0+g+8)*PCS + col];
            float v00 = C[nt][0] + p0.x, v01 = C[nt][1] + p0.y;
            float v10 = C[nt][2] + p1.x, v11 = C[nt][3] + p1.y;
            float a2d0 = P2[128+col], a2d1 = P2[128+col+1];
            float a2g0 = P2[192+col], a2g1 = P2[192+col+1];
            float r00, r01, r10, r11;
            {
                float sln = tanhf(a1d0 + a2d0);
                float gt  = 1.0f/(1.0f + expf(-(a1g0 + a2g0 + bgk)));
                r00 = uk*(gt*v00 + (1.0f-gt)*sln + bk);
                sln = tanhf(a1d0 + a2d1);
                gt  = 1.0f/(1.0f + expf(-(a1g0 + a2g1 + bgk)));
                r01 = uk*(gt*v01 + (1.0f-gt)*sln + bk);
                sln = tanhf(a1d1 + a2d0);
                gt  = 1.0f/(1.0f + expf(-(a1g1 + a2g0 + bgk)));
                r10 = uk*(gt*v10 + (1.0f-gt)*sln + bk);
                sln = tanhf(a1d1 + a2d1);
                gt  = 1.0f/(1.0f + expf(-(a1g1 + a2g1 + bgk)));
                r11 = uk*(gt*v11 + (1.0f-gt)*sln + bk);
            }
            *(float2*)&Sb[(m0+g)*Ln + col]   = make_float2(r00, r01);
            *(float2*)&Sb[(m0+g+8)*Ln + col] = make_float2(r10, r11);
        }
    }
}

// ---- deterministic split-k reduction: 2 threads per output ----
__global__ void reduce_kernel(float* __restrict__ out){
    __shared__ float red[128];
    int tid = threadIdx.x;
    int s = tid >> 1, h = tid & 1;
    int gmn = blockIdx.x*128 + s;           // 0..32767
    int b = gmn >> 12, mn = gmn & 4095;
    const float* p = g_S + (size_t)b*Kn*4096 + mn + h*16*4096;
    float acc = 0.f;
    #pragma unroll
    for(int kk = 0; kk < 16; kk++) acc += p[kk*4096];
    if(h) red[s] = acc;
    __syncthreads();
    if(!h) out[gmn] = acc + red[s];
}

extern "C" void kernel_launch(void* const* d_in, const int* in_sizes, int n_in,
                              void* d_out, int out_size){
    const float *arg1=0,*arg2=0,*Wb=0,*Wd=0,*Wg=0,*bg=0,*bb=0,*u=0;
    int nBig=0, nMed=0, nSmall=0;
    for(int i=0;i<n_in;i++){
        int sz = in_sizes[i];
        const float* pp = (const float*)d_in[i];
        if(sz == Kn*Dn*Dn)          Wb = pp;
        else if(sz == Bn*Ln*Dn)     { if(nBig++==0) arg1=pp; else arg2=pp; }
        else if(sz == 2*Dn*Kn)      { if(nMed++==0) Wd=pp;   else Wg=pp; }
        else if(sz == Kn)           { if(nSmall==0) bg=pp; else if(nSmall==1) bb=pp; else u=pp; nSmall++; }
    }
    float* out = (float*)d_out;

    static int attr_done = 0;
    if(!attr_done){
        cudaFuncSetAttribute(fused_kernel, cudaFuncAttributeMaxDynamicSharedMemorySize, SMEM_BYTES);
        attr_done = 1;
    }

    prep_kernel <<<1152, 256>>>(Wb, arg1, arg2);
    fused_kernel<<<Bn*Kn, 256, SMEM_BYTES>>>(arg1, arg2, Wd, Wg, bg, bb, u);
    reduce_kernel<<<256, 256>>>(out);
}